// round 5
// baseline (speedup 1.0000x reference)
#include <cuda_runtime.h>
#include <math.h>

#define NG 4096
#define W_IMG 256
#define H_IMG 256
#define TSZ 64
#define NTILE 16          // 4x4 tiles of 64x64

// Attrs: 0 mx, 1 my, 2 c00, 3 c11, 4 csum, 5 op, 6 r, 7 g, 8 b, 9 z,
//        10 rminx, 11 rmaxx, 12 rminy, 13 rmaxy
#define NATTR 14
#define NREND 10          // attrs needed by render

__device__ float g_zraw[NG];
__device__ float g_tmp[NATTR][NG];        // unsorted
__device__ float g_srt[NATTR][NG];        // sorted by z
__device__ float g_tile[NTILE][NREND][NG]; // per-tile compacted, sorted order
__device__ int   g_tilecnt[NTILE];

// ---------------------------------------------------------------------------
// Kernel 1: per-gaussian projection / preprocessing
// ---------------------------------------------------------------------------
__global__ void prep_kernel(const float* __restrict__ xyz,
                            const float* __restrict__ cov_world,
                            const float* __restrict__ colors,
                            const float* __restrict__ opacity,
                            const float* __restrict__ w2c,
                            const float* __restrict__ focal,
                            const float* __restrict__ pp)
{
    int i = blockIdx.x * blockDim.x + threadIdx.x;
    if (i >= NG) return;

    float R00 = w2c[0],  R01 = w2c[1],  R02 = w2c[2],  t0 = w2c[3];
    float R10 = w2c[4],  R11 = w2c[5],  R12 = w2c[6],  t1 = w2c[7];
    float R20 = w2c[8],  R21 = w2c[9],  R22 = w2c[10], t2 = w2c[11];

    float p0 = xyz[i*3+0], p1 = xyz[i*3+1], p2 = xyz[i*3+2];
    float cam0 = R00*p0 + R01*p1 + R02*p2 + t0;
    float cam1 = R10*p0 + R11*p1 + R12*p2 + t1;
    float cam2 = R20*p0 + R21*p1 + R22*p2 + t2;

    float zr = cam2;
    float z  = fmaxf(zr, 1e-6f);
    float fx = focal[0], fy = focal[1];
    float mx = fx * cam0 / z + pp[0];
    float my = fy * cam1 / z + pp[1];

    // cov_cam = R * S * R^T
    float S[3][3];
    #pragma unroll
    for (int r = 0; r < 3; r++)
        #pragma unroll
        for (int c = 0; c < 3; c++)
            S[r][c] = cov_world[i*9 + r*3 + c];

    float Rm[3][3] = {{R00,R01,R02},{R10,R11,R12},{R20,R21,R22}};
    float M[3][3], C[3][3];
    #pragma unroll
    for (int r = 0; r < 3; r++)
        #pragma unroll
        for (int c = 0; c < 3; c++)
            M[r][c] = Rm[r][0]*S[0][c] + Rm[r][1]*S[1][c] + Rm[r][2]*S[2][c];
    #pragma unroll
    for (int r = 0; r < 3; r++)
        #pragma unroll
        for (int c = 0; c < 3; c++)
            C[r][c] = M[r][0]*Rm[c][0] + M[r][1]*Rm[c][1] + M[r][2]*Rm[c][2];

    float J00 = fx / z, J02 = -fx * cam0 / (z * z);
    float J11 = fy / z, J12 = -fy * cam1 / (z * z);
    float t0v0 = J00*C[0][0] + J02*C[2][0];
    float t0v1 = J00*C[0][1] + J02*C[2][1];
    float t0v2 = J00*C[0][2] + J02*C[2][2];
    float t1v0 = J11*C[1][0] + J12*C[2][0];
    float t1v1 = J11*C[1][1] + J12*C[2][1];
    float t1v2 = J11*C[1][2] + J12*C[2][2];

    float a = t0v0*J00 + t0v2*J02 + 0.3f;
    float b = t0v1*J11 + t0v2*J12;
    float c = t1v0*J00 + t1v2*J02;
    float d = t1v1*J11 + t1v2*J12 + 0.3f;

    float disc   = sqrtf(fmaxf(0.25f*(a-d)*(a-d) + b*c, 0.0f));
    float maxeig = fmaxf(0.5f*(a+d) + disc, 1e-8f);
    float radius = fminf(3.0f * sqrtf(maxeig), 64.0f);
    float det    = a*d - b*c;
    float c00  = d / det;
    float c11  = a / det;
    float csum = (-b - c) / det;

    float opv = opacity[i];
    bool valid = (zr > 0.1f) && (opv > 1e-4f) && (radius > 0.25f);
    valid = valid && (mx + radius >= -1.0f) && (mx - radius < (float)W_IMG + 1.0f);
    valid = valid && (my + radius >= -1.0f) && (my - radius < (float)H_IMG + 1.0f);

    float radii = ceilf(radius);
    float rminx = fminf(fmaxf(floorf(mx - radii), 0.0f), (float)(W_IMG - 1));
    float rmaxx = fminf(fmaxf(ceilf (mx + radii), 0.0f), (float)(W_IMG - 1));
    float rminy = fminf(fmaxf(floorf(my - radii), 0.0f), (float)(H_IMG - 1));
    float rmaxy = fminf(fmaxf(ceilf (my + radii), 0.0f), (float)(H_IMG - 1));
    if (!valid) { rminx = 1e9f; rmaxx = -1e9f; rminy = 1e9f; rmaxy = -1e9f; }

    g_zraw[i]     = zr;
    g_tmp[0][i]   = mx;
    g_tmp[1][i]   = my;
    g_tmp[2][i]   = c00;
    g_tmp[3][i]   = c11;
    g_tmp[4][i]   = csum;
    g_tmp[5][i]   = opv;
    g_tmp[6][i]   = colors[i*3+0];
    g_tmp[7][i]   = colors[i*3+1];
    g_tmp[8][i]   = colors[i*3+2];
    g_tmp[9][i]   = zr;
    g_tmp[10][i]  = rminx;
    g_tmp[11][i]  = rmaxx;
    g_tmp[12][i]  = rminy;
    g_tmp[13][i]  = rmaxy;
}

// ---------------------------------------------------------------------------
// Kernel 2: stable rank-sort by z (vectorized O(N^2) vs shared z) + scatter
// ---------------------------------------------------------------------------
__global__ void sort_scatter_kernel()
{
    __shared__ float zsh[NG];
    for (int j = threadIdx.x; j < NG; j += blockDim.x)
        zsh[j] = g_zraw[j];
    __syncthreads();

    int i = blockIdx.x * blockDim.x + threadIdx.x;
    if (i >= NG) return;
    float zi = zsh[i];
    const float4* z4 = (const float4*)zsh;
    int rank = 0;
    #pragma unroll 4
    for (int j4 = 0; j4 < NG / 4; j4++) {
        float4 v = z4[j4];
        int j = j4 * 4;
        rank += (v.x < zi) || (v.x == zi && (j+0) < i);
        rank += (v.y < zi) || (v.y == zi && (j+1) < i);
        rank += (v.z < zi) || (v.z == zi && (j+2) < i);
        rank += (v.w < zi) || (v.w == zi && (j+3) < i);
    }
    #pragma unroll
    for (int k = 0; k < NATTR; k++)
        g_srt[k][rank] = g_tmp[k][i];
}

// ---------------------------------------------------------------------------
// Kernel 3: per-tile binning. One block per 64x64 tile; order-preserving
// compaction of sorted gaussians that overlap the tile (exact reference
// tile-overlap predicate) into attribute-major per-tile lists.
// ---------------------------------------------------------------------------
__global__ void __launch_bounds__(256)
bin_kernel()
{
    const int t  = blockIdx.x;
    const float x0f = (float)((t & 3) * TSZ);
    const float y0f = (float)((t >> 2) * TSZ);

    __shared__ int warp_cnt[8];
    const int warp = threadIdx.x >> 5;
    const int lane = threadIdx.x & 31;

    int offset = 0;
    for (int base = 0; base < NG; base += 256) {
        int gi = base + threadIdx.x;
        float rminx = g_srt[10][gi];
        float rmaxx = g_srt[11][gi];
        float rminy = g_srt[12][gi];
        float rmaxy = g_srt[13][gi];
        bool pred = (rmaxx >= x0f) && (rminx < x0f + (float)TSZ) &&
                    (rmaxy >= y0f) && (rminy < y0f + (float)TSZ);

        unsigned mask = __ballot_sync(0xffffffffu, pred);
        if (lane == 0) warp_cnt[warp] = __popc(mask);
        __syncthreads();

        int woff = 0, cnt = 0;
        #pragma unroll
        for (int w = 0; w < 8; w++) {
            int c = warp_cnt[w];
            if (w < warp) woff += c;
            cnt += c;
        }
        if (pred) {
            int pos = offset + woff + __popc(mask & ((1u << lane) - 1u));
            #pragma unroll
            for (int a = 0; a < NREND; a++)
                g_tile[t][a][pos] = g_srt[a][gi];
        }
        offset += cnt;
        __syncthreads();
    }
    if (threadIdx.x == 0) g_tilecnt[t] = offset;
}

// ---------------------------------------------------------------------------
// Kernel 4: rasterizer. One block = 16x16 pixels (1 px/thread), 16 blocks
// per tile. Streams the tile's pre-binned list through shared memory.
// ---------------------------------------------------------------------------
__global__ void __launch_bounds__(256)
render_kernel(const float* __restrict__ bg, float* __restrict__ out)
{
    const int bx = blockIdx.x & 15;
    const int by = blockIdx.x >> 4;
    const int px = bx * 16 + (threadIdx.x & 15);
    const int py = by * 16 + (threadIdx.x >> 4);
    const int t  = (by >> 2) * 4 + (bx >> 2);

    const float cx = (float)px + 0.5f;
    const float cy = (float)py + 0.5f;

    __shared__ float s_a[NREND][256];

    float T = 1.0f;
    float accR = 0.f, accG = 0.f, accB = 0.f, acc = 0.f, dnum = 0.f;

    const int cnt = g_tilecnt[t];

    for (int base = 0; base < cnt; base += 256) {
        int idx = base + threadIdx.x;
        if (idx < cnt) {
            #pragma unroll
            for (int a = 0; a < NREND; a++)
                s_a[a][threadIdx.x] = g_tile[t][a][idx];
        }
        __syncthreads();

        int m = cnt - base; if (m > 256) m = 256;
        for (int k = 0; k < m; k++) {
            float dx = cx - s_a[0][k];
            float dy = cy - s_a[1][k];
            float maha = dx*dx*s_a[2][k] + dy*dy*s_a[3][k] + dx*dy*s_a[4][k];
            if (maha <= 9.0f) {               // NaN -> false, matches jnp.where
                float alpha = fminf(__expf(-0.5f * maha) * s_a[5][k], 0.99f);
                if (alpha >= (1.0f / 255.0f)) {
                    float w = T * alpha;
                    accR += w * s_a[6][k];
                    accG += w * s_a[7][k];
                    accB += w * s_a[8][k];
                    acc  += w;
                    dnum += w * s_a[9][k];
                    T *= (1.0f - alpha);
                }
            }
        }

        if (__syncthreads_and(T < 1e-7f)) break;   // also the chunk barrier
    }

    float bgr = bg[0], bgg = bg[1], bgb = bg[2];
    float Rv = accR + (1.0f - acc) * bgr;
    float Gv = accG + (1.0f - acc) * bgg;
    float Bv = accB + (1.0f - acc) * bgb;
    Rv = fminf(fmaxf(Rv, 0.0f), 1.0f);
    Gv = fminf(fmaxf(Gv, 0.0f), 1.0f);
    Bv = fminf(fmaxf(Bv, 0.0f), 1.0f);
    float A = fminf(fmaxf(acc, 0.0f), 1.0f);
    float depth = (acc > 0.0f) ? (dnum / fmaxf(acc, 1e-8f)) : 0.0f;

    int o = (py * W_IMG + px) * 5;
    out[o+0] = Rv;
    out[o+1] = Gv;
    out[o+2] = Bv;
    out[o+3] = A;
    out[o+4] = depth;
}

// ---------------------------------------------------------------------------
extern "C" void kernel_launch(void* const* d_in, const int* in_sizes, int n_in,
                              void* d_out, int out_size)
{
    const float* xyz     = (const float*)d_in[0];
    const float* cov     = (const float*)d_in[1];
    const float* colors  = (const float*)d_in[2];
    const float* opacity = (const float*)d_in[3];
    const float* w2c     = (const float*)d_in[4];
    const float* focal   = (const float*)d_in[5];
    const float* pp      = (const float*)d_in[6];
    const float* bg      = (const float*)d_in[7];
    float* out = (float*)d_out;

    prep_kernel<<<NG / 256, 256>>>(xyz, cov, colors, opacity, w2c, focal, pp);
    sort_scatter_kernel<<<NG / 256, 256>>>();
    bin_kernel<<<NTILE, 256>>>();
    render_kernel<<<(W_IMG / 16) * (H_IMG / 16), 256>>>(bg, out);
}

// round 6
// speedup vs baseline: 1.9206x; 1.9206x over previous
#include <cuda_runtime.h>
#include <math.h>

#define NG 4096
#define W_IMG 256
#define H_IMG 256
#define TSZ 64
#define NBLK 256           // 16x16 grid of 16x16-pixel blocks
#define NREND 10           // attrs needed by render

// unsorted per-gaussian data
__device__ float  g_zraw[NG];
__device__ int    g_rank[NG];
__device__ float  g_tmp[NREND][NG];      // mx,my,c00,c11,csum,op,r,g,b,z
__device__ float4 g_tmpbb[NG];           // tile-test bbox  (rminx,rmaxx,rminy,rmaxy)
__device__ float4 g_tmpbbb[NG];          // block-refine bbox (inf when radius clipped)

// z-sorted
__device__ float  g_sa[NREND][NG];
__device__ float4 g_sbb[NG];
__device__ float4 g_sbbb[NG];

// per-16x16-block compacted lists (attribute-major, sorted order)
__device__ float  g_blk[NBLK][NREND][NG];
__device__ int    g_blkcnt[NBLK];

// ---------------------------------------------------------------------------
// Kernel 1: projection / preprocessing (also zeroes g_rank for this replay)
// ---------------------------------------------------------------------------
__global__ void prep_kernel(const float* __restrict__ xyz,
                            const float* __restrict__ cov_world,
                            const float* __restrict__ colors,
                            const float* __restrict__ opacity,
                            const float* __restrict__ w2c,
                            const float* __restrict__ focal,
                            const float* __restrict__ pp)
{
    int i = blockIdx.x * blockDim.x + threadIdx.x;
    if (i >= NG) return;

    float R00 = w2c[0],  R01 = w2c[1],  R02 = w2c[2],  t0 = w2c[3];
    float R10 = w2c[4],  R11 = w2c[5],  R12 = w2c[6],  t1 = w2c[7];
    float R20 = w2c[8],  R21 = w2c[9],  R22 = w2c[10], t2 = w2c[11];

    float p0 = xyz[i*3+0], p1 = xyz[i*3+1], p2 = xyz[i*3+2];
    float cam0 = R00*p0 + R01*p1 + R02*p2 + t0;
    float cam1 = R10*p0 + R11*p1 + R12*p2 + t1;
    float cam2 = R20*p0 + R21*p1 + R22*p2 + t2;

    float zr = cam2;
    float z  = fmaxf(zr, 1e-6f);
    float fx = focal[0], fy = focal[1];
    float mx = fx * cam0 / z + pp[0];
    float my = fy * cam1 / z + pp[1];

    // cov_cam = R * S * R^T
    float S[3][3];
    #pragma unroll
    for (int r = 0; r < 3; r++)
        #pragma unroll
        for (int c = 0; c < 3; c++)
            S[r][c] = cov_world[i*9 + r*3 + c];

    float Rm[3][3] = {{R00,R01,R02},{R10,R11,R12},{R20,R21,R22}};
    float M[3][3], C[3][3];
    #pragma unroll
    for (int r = 0; r < 3; r++)
        #pragma unroll
        for (int c = 0; c < 3; c++)
            M[r][c] = Rm[r][0]*S[0][c] + Rm[r][1]*S[1][c] + Rm[r][2]*S[2][c];
    #pragma unroll
    for (int r = 0; r < 3; r++)
        #pragma unroll
        for (int c = 0; c < 3; c++)
            C[r][c] = M[r][0]*Rm[c][0] + M[r][1]*Rm[c][1] + M[r][2]*Rm[c][2];

    float J00 = fx / z, J02 = -fx * cam0 / (z * z);
    float J11 = fy / z, J12 = -fy * cam1 / (z * z);
    float t0v0 = J00*C[0][0] + J02*C[2][0];
    float t0v1 = J00*C[0][1] + J02*C[2][1];
    float t0v2 = J00*C[0][2] + J02*C[2][2];
    float t1v0 = J11*C[1][0] + J12*C[2][0];
    float t1v1 = J11*C[1][1] + J12*C[2][1];
    float t1v2 = J11*C[1][2] + J12*C[2][2];

    float a = t0v0*J00 + t0v2*J02 + 0.3f;
    float b = t0v1*J11 + t0v2*J12;
    float c = t1v0*J00 + t1v2*J02;
    float d = t1v1*J11 + t1v2*J12 + 0.3f;

    float disc   = sqrtf(fmaxf(0.25f*(a-d)*(a-d) + b*c, 0.0f));
    float maxeig = fmaxf(0.5f*(a+d) + disc, 1e-8f);
    float rraw   = 3.0f * sqrtf(maxeig);
    float radius = fminf(rraw, 64.0f);
    float det    = a*d - b*c;
    float c00  = d / det;
    float c11  = a / det;
    float csum = (-b - c) / det;

    float opv = opacity[i];
    bool valid = (zr > 0.1f) && (opv > 1e-4f) && (radius > 0.25f);
    valid = valid && (mx + radius >= -1.0f) && (mx - radius < (float)W_IMG + 1.0f);
    valid = valid && (my + radius >= -1.0f) && (my - radius < (float)H_IMG + 1.0f);

    float radii = ceilf(radius);
    float rminx = fminf(fmaxf(floorf(mx - radii), 0.0f), (float)(W_IMG - 1));
    float rmaxx = fminf(fmaxf(ceilf (mx + radii), 0.0f), (float)(W_IMG - 1));
    float rminy = fminf(fmaxf(floorf(my - radii), 0.0f), (float)(H_IMG - 1));
    float rmaxy = fminf(fmaxf(ceilf (my + radii), 0.0f), (float)(H_IMG - 1));

    float4 bb, bbb;
    if (!valid) {
        bb  = make_float4(1e9f, -1e9f, 1e9f, -1e9f);
        bbb = bb;
    } else {
        bb = make_float4(rminx, rmaxx, rminy, rmaxy);
        // radius clipped -> 3-sigma ellipse may exceed bbox: refine conservatively
        bbb = (rraw > 64.0f) ? make_float4(-1e9f, 1e9f, -1e9f, 1e9f) : bb;
    }

    g_zraw[i]   = zr;
    g_rank[i]   = 0;
    g_tmp[0][i] = mx;
    g_tmp[1][i] = my;
    g_tmp[2][i] = c00;
    g_tmp[3][i] = c11;
    g_tmp[4][i] = csum;
    g_tmp[5][i] = opv;
    g_tmp[6][i] = colors[i*3+0];
    g_tmp[7][i] = colors[i*3+1];
    g_tmp[8][i] = colors[i*3+2];
    g_tmp[9][i] = zr;
    g_tmpbb[i]  = bb;
    g_tmpbbb[i] = bbb;
}

// ---------------------------------------------------------------------------
// Kernel 2: partial stable rank. grid = (16 i-chunks, 16 j-chunks).
// Each block compares its 256 i's against one 256-element j-chunk.
// ---------------------------------------------------------------------------
__global__ void __launch_bounds__(256)
rank_kernel()
{
    __shared__ float zsh[256];
    const int ibase = blockIdx.x * 256;
    const int jbase = blockIdx.y * 256;
    const int tid = threadIdx.x;

    zsh[tid] = g_zraw[jbase + tid];
    __syncthreads();

    const int i = ibase + tid;
    const float zi = g_zraw[i];
    const float4* z4 = (const float4*)zsh;
    int partial = 0;
    #pragma unroll 8
    for (int j4 = 0; j4 < 64; j4++) {
        float4 v = z4[j4];
        int j = jbase + j4 * 4;
        partial += (v.x < zi) || (v.x == zi && (j+0) < i);
        partial += (v.y < zi) || (v.y == zi && (j+1) < i);
        partial += (v.z < zi) || (v.z == zi && (j+2) < i);
        partial += (v.w < zi) || (v.w == zi && (j+3) < i);
    }
    atomicAdd(&g_rank[i], partial);
}

// ---------------------------------------------------------------------------
// Kernel 3: scatter to sorted order
// ---------------------------------------------------------------------------
__global__ void scatter_kernel()
{
    int i = blockIdx.x * blockDim.x + threadIdx.x;
    if (i >= NG) return;
    int r = g_rank[i];
    #pragma unroll
    for (int a = 0; a < NREND; a++)
        g_sa[a][r] = g_tmp[a][i];
    g_sbb[r]  = g_tmpbb[i];
    g_sbbb[r] = g_tmpbbb[i];
}

// ---------------------------------------------------------------------------
// Kernel 4: per-16x16-block binning. 256 blocks, one per image block.
// Predicate = reference tile-level overlap AND refine-bbox vs this block.
// Order-preserving compaction; writes attribute-major lists.
// ---------------------------------------------------------------------------
__global__ void __launch_bounds__(256)
bin_kernel()
{
    const int bl = blockIdx.x;
    const int bx = bl & 15, by = bl >> 4;
    const float x0f = (float)((bx >> 2) * TSZ);        // owning 64x64 tile
    const float y0f = (float)((by >> 2) * TSZ);
    const float bx0 = (float)(bx * 16);                 // 16x16 block
    const float by0 = (float)(by * 16);

    __shared__ int warp_cnt[8];
    const int warp = threadIdx.x >> 5;
    const int lane = threadIdx.x & 31;

    int offset = 0;
    for (int base = 0; base < NG; base += 256) {
        int gi = base + threadIdx.x;
        float4 bb  = g_sbb[gi];
        float4 bbb = g_sbbb[gi];
        bool pred = (bb.y >= x0f) && (bb.x < x0f + (float)TSZ) &&
                    (bb.w >= y0f) && (bb.z < y0f + (float)TSZ) &&
                    (bbb.y >= bx0) && (bbb.x < bx0 + 16.0f) &&
                    (bbb.w >= by0) && (bbb.z < by0 + 16.0f);

        unsigned mask = __ballot_sync(0xffffffffu, pred);
        if (lane == 0) warp_cnt[warp] = __popc(mask);
        __syncthreads();

        int woff = 0, cnt = 0;
        #pragma unroll
        for (int w = 0; w < 8; w++) {
            int c = warp_cnt[w];
            if (w < warp) woff += c;
            cnt += c;
        }
        if (pred) {
            int pos = offset + woff + __popc(mask & ((1u << lane) - 1u));
            #pragma unroll
            for (int a = 0; a < NREND; a++)
                g_blk[bl][a][pos] = g_sa[a][gi];
        }
        offset += cnt;
        __syncthreads();
    }
    if (threadIdx.x == 0) g_blkcnt[bl] = offset;
}

// ---------------------------------------------------------------------------
// Kernel 5: rasterizer. One block = its 16x16 pixel block, short list.
// ---------------------------------------------------------------------------
__global__ void __launch_bounds__(256)
render_kernel(const float* __restrict__ bg, float* __restrict__ out)
{
    const int bl = blockIdx.x;
    const int px = (bl & 15) * 16 + (threadIdx.x & 15);
    const int py = (bl >> 4) * 16 + (threadIdx.x >> 4);
    const float cx = (float)px + 0.5f;
    const float cy = (float)py + 0.5f;

    __shared__ float s_a[NREND][256];

    float T = 1.0f;
    float accR = 0.f, accG = 0.f, accB = 0.f, acc = 0.f, dnum = 0.f;

    const int cnt = g_blkcnt[bl];

    for (int base = 0; base < cnt; base += 256) {
        int idx = base + threadIdx.x;
        if (idx < cnt) {
            #pragma unroll
            for (int a = 0; a < NREND; a++)
                s_a[a][threadIdx.x] = g_blk[bl][a][idx];
        }
        __syncthreads();

        int m = cnt - base; if (m > 256) m = 256;
        for (int k = 0; k < m; k++) {
            float dx = cx - s_a[0][k];
            float dy = cy - s_a[1][k];
            float maha = dx*dx*s_a[2][k] + dy*dy*s_a[3][k] + dx*dy*s_a[4][k];
            if (maha <= 9.0f) {               // NaN -> false, matches jnp.where
                float alpha = fminf(__expf(-0.5f * maha) * s_a[5][k], 0.99f);
                if (alpha >= (1.0f / 255.0f)) {
                    float w = T * alpha;
                    accR += w * s_a[6][k];
                    accG += w * s_a[7][k];
                    accB += w * s_a[8][k];
                    acc  += w;
                    dnum += w * s_a[9][k];
                    T *= (1.0f - alpha);
                }
            }
        }

        if (base + 256 < cnt) {
            if (__syncthreads_and(T < 1e-7f)) break;
        }
    }

    float bgr = bg[0], bgg = bg[1], bgb = bg[2];
    float Rv = accR + (1.0f - acc) * bgr;
    float Gv = accG + (1.0f - acc) * bgg;
    float Bv = accB + (1.0f - acc) * bgb;
    Rv = fminf(fmaxf(Rv, 0.0f), 1.0f);
    Gv = fminf(fmaxf(Gv, 0.0f), 1.0f);
    Bv = fminf(fmaxf(Bv, 0.0f), 1.0f);
    float A = fminf(fmaxf(acc, 0.0f), 1.0f);
    float depth = (acc > 0.0f) ? (dnum / fmaxf(acc, 1e-8f)) : 0.0f;

    int o = (py * W_IMG + px) * 5;
    out[o+0] = Rv;
    out[o+1] = Gv;
    out[o+2] = Bv;
    out[o+3] = A;
    out[o+4] = depth;
}

// ---------------------------------------------------------------------------
extern "C" void kernel_launch(void* const* d_in, const int* in_sizes, int n_in,
                              void* d_out, int out_size)
{
    const float* xyz     = (const float*)d_in[0];
    const float* cov     = (const float*)d_in[1];
    const float* colors  = (const float*)d_in[2];
    const float* opacity = (const float*)d_in[3];
    const float* w2c     = (const float*)d_in[4];
    const float* focal   = (const float*)d_in[5];
    const float* pp      = (const float*)d_in[6];
    const float* bg      = (const float*)d_in[7];
    float* out = (float*)d_out;

    prep_kernel<<<NG / 64, 64>>>(xyz, cov, colors, opacity, w2c, focal, pp);
    rank_kernel<<<dim3(16, 16), 256>>>();
    scatter_kernel<<<NG / 256, 256>>>();
    bin_kernel<<<NBLK, 256>>>();
    render_kernel<<<NBLK, 256>>>(bg, out);
}

// round 7
// speedup vs baseline: 3.6091x; 1.8792x over previous
#include <cuda_runtime.h>
#include <math.h>

#define NG 4096
#define W_IMG 256
#define H_IMG 256
#define TSZ 64
#define NBLK 256           // 16x16 grid of 16x16-pixel blocks
#define GPT 16             // gaussians per thread in strip-scan bin

// unsorted per-gaussian data (attr-packed)
__device__ float  g_zraw[NG];
__device__ int    g_rank[NG];
__device__ float4 g_tA[NG];     // mx,my,c00,c11
__device__ float4 g_tB[NG];     // csum,op,r,g
__device__ float2 g_tC[NG];     // b,z
__device__ float4 g_tbb[NG];    // tile-test bbox (rminx,rmaxx,rminy,rmaxy)
__device__ float4 g_tbbb[NG];   // block-refine bbox (inf when radius clipped)

// z-sorted
__device__ float4 g_sA[NG];
__device__ float4 g_sB[NG];
__device__ float2 g_sC[NG];
__device__ float4 g_sbb[NG];
__device__ float4 g_sbbb[NG];

// per-16x16-block compacted lists (sorted order)
__device__ float4 g_bA[NBLK][NG];
__device__ float4 g_bB[NBLK][NG];
__device__ float2 g_bC[NBLK][NG];
__device__ int    g_blkcnt[NBLK];

// ---------------------------------------------------------------------------
// Kernel 1: projection / preprocessing
// ---------------------------------------------------------------------------
__global__ void prep_kernel(const float* __restrict__ xyz,
                            const float* __restrict__ cov_world,
                            const float* __restrict__ colors,
                            const float* __restrict__ opacity,
                            const float* __restrict__ w2c,
                            const float* __restrict__ focal,
                            const float* __restrict__ pp)
{
    int i = blockIdx.x * blockDim.x + threadIdx.x;
    if (i >= NG) return;

    float R00 = w2c[0],  R01 = w2c[1],  R02 = w2c[2],  t0 = w2c[3];
    float R10 = w2c[4],  R11 = w2c[5],  R12 = w2c[6],  t1 = w2c[7];
    float R20 = w2c[8],  R21 = w2c[9],  R22 = w2c[10], t2 = w2c[11];

    float p0 = xyz[i*3+0], p1 = xyz[i*3+1], p2 = xyz[i*3+2];
    float cam0 = R00*p0 + R01*p1 + R02*p2 + t0;
    float cam1 = R10*p0 + R11*p1 + R12*p2 + t1;
    float cam2 = R20*p0 + R21*p1 + R22*p2 + t2;

    float zr = cam2;
    float z  = fmaxf(zr, 1e-6f);
    float fx = focal[0], fy = focal[1];
    float mx = fx * cam0 / z + pp[0];
    float my = fy * cam1 / z + pp[1];

    float S[3][3];
    #pragma unroll
    for (int r = 0; r < 3; r++)
        #pragma unroll
        for (int c = 0; c < 3; c++)
            S[r][c] = cov_world[i*9 + r*3 + c];

    float Rm[3][3] = {{R00,R01,R02},{R10,R11,R12},{R20,R21,R22}};
    float M[3][3], C[3][3];
    #pragma unroll
    for (int r = 0; r < 3; r++)
        #pragma unroll
        for (int c = 0; c < 3; c++)
            M[r][c] = Rm[r][0]*S[0][c] + Rm[r][1]*S[1][c] + Rm[r][2]*S[2][c];
    #pragma unroll
    for (int r = 0; r < 3; r++)
        #pragma unroll
        for (int c = 0; c < 3; c++)
            C[r][c] = M[r][0]*Rm[c][0] + M[r][1]*Rm[c][1] + M[r][2]*Rm[c][2];

    float J00 = fx / z, J02 = -fx * cam0 / (z * z);
    float J11 = fy / z, J12 = -fy * cam1 / (z * z);
    float t0v0 = J00*C[0][0] + J02*C[2][0];
    float t0v1 = J00*C[0][1] + J02*C[2][1];
    float t0v2 = J00*C[0][2] + J02*C[2][2];
    float t1v0 = J11*C[1][0] + J12*C[2][0];
    float t1v1 = J11*C[1][1] + J12*C[2][1];
    float t1v2 = J11*C[1][2] + J12*C[2][2];

    float a = t0v0*J00 + t0v2*J02 + 0.3f;
    float b = t0v1*J11 + t0v2*J12;
    float c = t1v0*J00 + t1v2*J02;
    float d = t1v1*J11 + t1v2*J12 + 0.3f;

    float disc   = sqrtf(fmaxf(0.25f*(a-d)*(a-d) + b*c, 0.0f));
    float maxeig = fmaxf(0.5f*(a+d) + disc, 1e-8f);
    float rraw   = 3.0f * sqrtf(maxeig);
    float radius = fminf(rraw, 64.0f);
    float det    = a*d - b*c;
    float c00  = d / det;
    float c11  = a / det;
    float csum = (-b - c) / det;

    float opv = opacity[i];
    bool valid = (zr > 0.1f) && (opv > 1e-4f) && (radius > 0.25f);
    valid = valid && (mx + radius >= -1.0f) && (mx - radius < (float)W_IMG + 1.0f);
    valid = valid && (my + radius >= -1.0f) && (my - radius < (float)H_IMG + 1.0f);

    float radii = ceilf(radius);
    float rminx = fminf(fmaxf(floorf(mx - radii), 0.0f), (float)(W_IMG - 1));
    float rmaxx = fminf(fmaxf(ceilf (mx + radii), 0.0f), (float)(W_IMG - 1));
    float rminy = fminf(fmaxf(floorf(my - radii), 0.0f), (float)(H_IMG - 1));
    float rmaxy = fminf(fmaxf(ceilf (my + radii), 0.0f), (float)(H_IMG - 1));

    float4 bb, bbb;
    if (!valid) {
        bb  = make_float4(1e9f, -1e9f, 1e9f, -1e9f);
        bbb = bb;
    } else {
        bb = make_float4(rminx, rmaxx, rminy, rmaxy);
        // radius clipped -> 3-sigma ellipse may exceed bbox: refine conservatively
        bbb = (rraw > 64.0f) ? make_float4(-1e9f, 1e9f, -1e9f, 1e9f) : bb;
    }

    g_zraw[i] = zr;
    g_rank[i] = 0;
    g_tA[i] = make_float4(mx, my, c00, c11);
    g_tB[i] = make_float4(csum, opv, colors[i*3+0], colors[i*3+1]);
    g_tC[i] = make_float2(colors[i*3+2], zr);
    g_tbb[i]  = bb;
    g_tbbb[i] = bbb;
}

// ---------------------------------------------------------------------------
// Kernel 2: partial stable rank. grid = (16 i-chunks, 16 j-chunks).
// ---------------------------------------------------------------------------
__global__ void __launch_bounds__(256)
rank_kernel()
{
    __shared__ float zsh[256];
    const int ibase = blockIdx.x * 256;
    const int jbase = blockIdx.y * 256;
    const int tid = threadIdx.x;

    zsh[tid] = g_zraw[jbase + tid];
    __syncthreads();

    const int i = ibase + tid;
    const float zi = g_zraw[i];
    const float4* z4 = (const float4*)zsh;
    int partial = 0;
    #pragma unroll 8
    for (int j4 = 0; j4 < 64; j4++) {
        float4 v = z4[j4];
        int j = jbase + j4 * 4;
        partial += (v.x < zi) || (v.x == zi && (j+0) < i);
        partial += (v.y < zi) || (v.y == zi && (j+1) < i);
        partial += (v.z < zi) || (v.z == zi && (j+2) < i);
        partial += (v.w < zi) || (v.w == zi && (j+3) < i);
    }
    atomicAdd(&g_rank[i], partial);
}

// ---------------------------------------------------------------------------
// Kernel 3: scatter to sorted order
// ---------------------------------------------------------------------------
__global__ void scatter_kernel()
{
    int i = blockIdx.x * blockDim.x + threadIdx.x;
    if (i >= NG) return;
    int r = g_rank[i];
    g_sA[r]   = g_tA[i];
    g_sB[r]   = g_tB[i];
    g_sC[r]   = g_tC[i];
    g_sbb[r]  = g_tbb[i];
    g_sbbb[r] = g_tbbb[i];
}

// ---------------------------------------------------------------------------
// Kernel 4: per-16x16-block binning, single-pass strip scan.
// Thread t owns sorted strip [16t, 16t+16). Compute 16 predicates (high MLP),
// one block-wide exclusive scan (2 barriers), then ordered compact stores.
// ---------------------------------------------------------------------------
__global__ void __launch_bounds__(256)
bin_kernel()
{
    const int bl = blockIdx.x;
    const int bx = bl & 15, by = bl >> 4;
    const float x0f = (float)((bx >> 2) * TSZ);        // owning 64x64 tile
    const float y0f = (float)((by >> 2) * TSZ);
    const float bx0 = (float)(bx * 16);                 // 16x16 block
    const float by0 = (float)(by * 16);

    const int tid  = threadIdx.x;
    const int warp = tid >> 5;
    const int lane = tid & 31;
    const int base = tid * GPT;

    // --- predicate pass: 32 independent float4 loads, high MLP ---
    unsigned mmask = 0;
    int lc = 0;
    #pragma unroll
    for (int k = 0; k < GPT; k++) {
        float4 bb  = g_sbb[base + k];
        float4 bbb = g_sbbb[base + k];
        bool pred = (bb.y >= x0f) && (bb.x < x0f + (float)TSZ) &&
                    (bb.w >= y0f) && (bb.z < y0f + (float)TSZ) &&
                    (bbb.y >= bx0) && (bbb.x < bx0 + 16.0f) &&
                    (bbb.w >= by0) && (bbb.z < by0 + 16.0f);
        if (pred) { mmask |= (1u << k); lc++; }
    }

    // --- block-wide exclusive scan of lc (2 barriers) ---
    __shared__ int wsum[8];
    __shared__ int wpre[8];
    int v = lc;
    #pragma unroll
    for (int d2 = 1; d2 < 32; d2 <<= 1) {
        int n = __shfl_up_sync(0xffffffffu, v, d2);
        if (lane >= d2) v += n;
    }
    if (lane == 31) wsum[warp] = v;
    __syncthreads();
    if (tid < 8) {
        int s = wsum[tid];
        #pragma unroll
        for (int d2 = 1; d2 < 8; d2 <<= 1) {
            int n = __shfl_up_sync(0xffu, s, d2);
            if (tid >= d2) s += n;
        }
        wpre[tid] = s;
    }
    __syncthreads();

    int offset = ((warp == 0) ? 0 : wpre[warp - 1]) + (v - lc);

    // --- ordered compact stores ---
    unsigned mm = mmask;
    while (mm) {
        int k = __ffs(mm) - 1;
        mm &= mm - 1;
        int gi = base + k;
        g_bA[bl][offset] = g_sA[gi];
        g_bB[bl][offset] = g_sB[gi];
        g_bC[bl][offset] = g_sC[gi];
        offset++;
    }

    if (tid == 0) g_blkcnt[bl] = wpre[7];
}

// ---------------------------------------------------------------------------
// Kernel 5: rasterizer. One block = its 16x16 pixel block, short list.
// ---------------------------------------------------------------------------
__global__ void __launch_bounds__(256)
render_kernel(const float* __restrict__ bg, float* __restrict__ out)
{
    const int bl = blockIdx.x;
    const int px = (bl & 15) * 16 + (threadIdx.x & 15);
    const int py = (bl >> 4) * 16 + (threadIdx.x >> 4);
    const float cx = (float)px + 0.5f;
    const float cy = (float)py + 0.5f;

    __shared__ float4 sA[256];
    __shared__ float4 sB[256];
    __shared__ float2 sC[256];

    float T = 1.0f;
    float accR = 0.f, accG = 0.f, accB = 0.f, acc = 0.f, dnum = 0.f;

    const int cnt = g_blkcnt[bl];

    for (int base = 0; base < cnt; base += 256) {
        int idx = base + threadIdx.x;
        if (idx < cnt) {
            sA[threadIdx.x] = g_bA[bl][idx];
            sB[threadIdx.x] = g_bB[bl][idx];
            sC[threadIdx.x] = g_bC[bl][idx];
        }
        __syncthreads();

        int m = cnt - base; if (m > 256) m = 256;
        for (int k = 0; k < m; k++) {
            float4 A = sA[k];
            float dx = cx - A.x;
            float dy = cy - A.y;
            float4 B = sB[k];
            float maha = dx*dx*A.z + dy*dy*A.w + dx*dy*B.x;
            if (maha <= 9.0f) {               // NaN -> false, matches jnp.where
                float alpha = fminf(__expf(-0.5f * maha) * B.y, 0.99f);
                if (alpha >= (1.0f / 255.0f)) {
                    float2 Cv = sC[k];
                    float w = T * alpha;
                    accR += w * B.z;
                    accG += w * B.w;
                    accB += w * Cv.x;
                    acc  += w;
                    dnum += w * Cv.y;
                    T *= (1.0f - alpha);
                }
            }
        }

        if (base + 256 < cnt) {
            if (__syncthreads_and(T < 1e-7f)) break;
        }
    }

    float bgr = bg[0], bgg = bg[1], bgb = bg[2];
    float Rv = accR + (1.0f - acc) * bgr;
    float Gv = accG + (1.0f - acc) * bgg;
    float Bv = accB + (1.0f - acc) * bgb;
    Rv = fminf(fmaxf(Rv, 0.0f), 1.0f);
    Gv = fminf(fmaxf(Gv, 0.0f), 1.0f);
    Bv = fminf(fmaxf(Bv, 0.0f), 1.0f);
    float A = fminf(fmaxf(acc, 0.0f), 1.0f);
    float depth = (acc > 0.0f) ? (dnum / fmaxf(acc, 1e-8f)) : 0.0f;

    int o = (py * W_IMG + px) * 5;
    out[o+0] = Rv;
    out[o+1] = Gv;
    out[o+2] = Bv;
    out[o+3] = A;
    out[o+4] = depth;
}

// ---------------------------------------------------------------------------
extern "C" void kernel_launch(void* const* d_in, const int* in_sizes, int n_in,
                              void* d_out, int out_size)
{
    const float* xyz     = (const float*)d_in[0];
    const float* cov     = (const float*)d_in[1];
    const float* colors  = (const float*)d_in[2];
    const float* opacity = (const float*)d_in[3];
    const float* w2c     = (const float*)d_in[4];
    const float* focal   = (const float*)d_in[5];
    const float* pp      = (const float*)d_in[6];
    const float* bg      = (const float*)d_in[7];
    float* out = (float*)d_out;

    prep_kernel<<<NG / 64, 64>>>(xyz, cov, colors, opacity, w2c, focal, pp);
    rank_kernel<<<dim3(16, 16), 256>>>();
    scatter_kernel<<<NG / 256, 256>>>();
    bin_kernel<<<NBLK, 256>>>();
    render_kernel<<<NBLK, 256>>>(bg, out);
}

// round 8
// speedup vs baseline: 4.3213x; 1.1973x over previous
#include <cuda_runtime.h>
#include <math.h>

#define NG 4096
#define W_IMG 256
#define H_IMG 256
#define TSZ 64
#define NBLK 256           // 16x16 grid of 16x16-pixel blocks
#define GPT 16             // gaussians per thread in strip scan

// unsorted per-gaussian data (attr-packed)
__device__ float  g_zraw[NG];
__device__ int    g_rank[NG];
__device__ float4 g_tA[NG];     // mx,my,c00,c11
__device__ float4 g_tB[NG];     // csum,op,r,g
__device__ float2 g_tC[NG];     // b,z
__device__ uint2  g_tpb[NG];    // packed bbox bytes {xmin,xmax,ymin,ymax} | flags (1=clipped)

// z-sorted
__device__ float4 g_sA[NG];
__device__ float4 g_sB[NG];
__device__ float2 g_sC[NG];
__device__ uint2  g_spb[NG];

// ---------------------------------------------------------------------------
// Kernel 1: projection / preprocessing
// ---------------------------------------------------------------------------
__global__ void prep_kernel(const float* __restrict__ xyz,
                            const float* __restrict__ cov_world,
                            const float* __restrict__ colors,
                            const float* __restrict__ opacity,
                            const float* __restrict__ w2c,
                            const float* __restrict__ focal,
                            const float* __restrict__ pp)
{
    int i = blockIdx.x * blockDim.x + threadIdx.x;
    if (i >= NG) return;

    float R00 = w2c[0],  R01 = w2c[1],  R02 = w2c[2],  t0 = w2c[3];
    float R10 = w2c[4],  R11 = w2c[5],  R12 = w2c[6],  t1 = w2c[7];
    float R20 = w2c[8],  R21 = w2c[9],  R22 = w2c[10], t2 = w2c[11];

    float p0 = xyz[i*3+0], p1 = xyz[i*3+1], p2 = xyz[i*3+2];
    float cam0 = R00*p0 + R01*p1 + R02*p2 + t0;
    float cam1 = R10*p0 + R11*p1 + R12*p2 + t1;
    float cam2 = R20*p0 + R21*p1 + R22*p2 + t2;

    float zr = cam2;
    float z  = fmaxf(zr, 1e-6f);
    float fx = focal[0], fy = focal[1];
    float mx = fx * cam0 / z + pp[0];
    float my = fy * cam1 / z + pp[1];

    float S[3][3];
    #pragma unroll
    for (int r = 0; r < 3; r++)
        #pragma unroll
        for (int c = 0; c < 3; c++)
            S[r][c] = cov_world[i*9 + r*3 + c];

    float Rm[3][3] = {{R00,R01,R02},{R10,R11,R12},{R20,R21,R22}};
    float M[3][3], C[3][3];
    #pragma unroll
    for (int r = 0; r < 3; r++)
        #pragma unroll
        for (int c = 0; c < 3; c++)
            M[r][c] = Rm[r][0]*S[0][c] + Rm[r][1]*S[1][c] + Rm[r][2]*S[2][c];
    #pragma unroll
    for (int r = 0; r < 3; r++)
        #pragma unroll
        for (int c = 0; c < 3; c++)
            C[r][c] = M[r][0]*Rm[c][0] + M[r][1]*Rm[c][1] + M[r][2]*Rm[c][2];

    float J00 = fx / z, J02 = -fx * cam0 / (z * z);
    float J11 = fy / z, J12 = -fy * cam1 / (z * z);
    float t0v0 = J00*C[0][0] + J02*C[2][0];
    float t0v1 = J00*C[0][1] + J02*C[2][1];
    float t0v2 = J00*C[0][2] + J02*C[2][2];
    float t1v0 = J11*C[1][0] + J12*C[2][0];
    float t1v1 = J11*C[1][1] + J12*C[2][1];
    float t1v2 = J11*C[1][2] + J12*C[2][2];

    float a = t0v0*J00 + t0v2*J02 + 0.3f;
    float b = t0v1*J11 + t0v2*J12;
    float c = t1v0*J00 + t1v2*J02;
    float d = t1v1*J11 + t1v2*J12 + 0.3f;

    float disc   = sqrtf(fmaxf(0.25f*(a-d)*(a-d) + b*c, 0.0f));
    float maxeig = fmaxf(0.5f*(a+d) + disc, 1e-8f);
    float rraw   = 3.0f * sqrtf(maxeig);
    float radius = fminf(rraw, 64.0f);
    float det    = a*d - b*c;
    float c00  = d / det;
    float c11  = a / det;
    float csum = (-b - c) / det;

    float opv = opacity[i];
    bool valid = (zr > 0.1f) && (opv > 1e-4f) && (radius > 0.25f);
    valid = valid && (mx + radius >= -1.0f) && (mx - radius < (float)W_IMG + 1.0f);
    valid = valid && (my + radius >= -1.0f) && (my - radius < (float)H_IMG + 1.0f);

    float radii = ceilf(radius);
    int ixmin = (int)fminf(fmaxf(floorf(mx - radii), 0.0f), 255.0f);
    int ixmax = (int)fminf(fmaxf(ceilf (mx + radii), 0.0f), 255.0f);
    int iymin = (int)fminf(fmaxf(floorf(my - radii), 0.0f), 255.0f);
    int iymax = (int)fminf(fmaxf(ceilf (my + radii), 0.0f), 255.0f);

    uint2 pb;
    if (!valid) {
        pb.x = 255u | (0u << 8) | (255u << 16) | (0u << 24);   // empty
        pb.y = 0u;
    } else {
        pb.x = (unsigned)ixmin | ((unsigned)ixmax << 8) |
               ((unsigned)iymin << 16) | ((unsigned)iymax << 24);
        pb.y = (rraw > 64.0f) ? 1u : 0u;   // clipped: ellipse may exceed bbox
    }

    g_zraw[i] = zr;
    g_rank[i] = 0;
    g_tA[i] = make_float4(mx, my, c00, c11);
    g_tB[i] = make_float4(csum, opv, colors[i*3+0], colors[i*3+1]);
    g_tC[i] = make_float2(colors[i*3+2], zr);
    g_tpb[i] = pb;
}

// ---------------------------------------------------------------------------
// Kernel 2: partial stable rank. grid = (16 i-chunks, 16 j-chunks).
// ---------------------------------------------------------------------------
__global__ void __launch_bounds__(256)
rank_kernel()
{
    __shared__ float zsh[256];
    const int ibase = blockIdx.x * 256;
    const int jbase = blockIdx.y * 256;
    const int tid = threadIdx.x;

    zsh[tid] = g_zraw[jbase + tid];
    __syncthreads();

    const int i = ibase + tid;
    const float zi = g_zraw[i];
    const float4* z4 = (const float4*)zsh;
    int partial = 0;
    #pragma unroll 8
    for (int j4 = 0; j4 < 64; j4++) {
        float4 v = z4[j4];
        int j = jbase + j4 * 4;
        partial += (v.x < zi) || (v.x == zi && (j+0) < i);
        partial += (v.y < zi) || (v.y == zi && (j+1) < i);
        partial += (v.z < zi) || (v.z == zi && (j+2) < i);
        partial += (v.w < zi) || (v.w == zi && (j+3) < i);
    }
    atomicAdd(&g_rank[i], partial);
}

// ---------------------------------------------------------------------------
// Kernel 3: scatter to sorted order
// ---------------------------------------------------------------------------
__global__ void scatter_kernel()
{
    int i = blockIdx.x * blockDim.x + threadIdx.x;
    if (i >= NG) return;
    int r = g_rank[i];
    g_sA[r]  = g_tA[i];
    g_sB[r]  = g_tB[i];
    g_sC[r]  = g_tC[i];
    g_spb[r] = g_tpb[i];
}

// ---------------------------------------------------------------------------
// Kernel 4: fused bin + rasterize. One block = one 16x16 pixel block.
// Phase A: strip-scan predicates over the full sorted list (8B/gaussian),
//          block-wide scan, compacted *index* list in shared (order kept).
// Phase B: composite in 256-entry chunks, gathering attrs into shared.
// ---------------------------------------------------------------------------
__global__ void __launch_bounds__(256)
render_kernel(const float* __restrict__ bg, float* __restrict__ out)
{
    const int bl = blockIdx.x;
    const int bx = bl & 15, by = bl >> 4;
    const int tx0 = (bx >> 2) * TSZ;      // owning 64x64 tile origin
    const int ty0 = (by >> 2) * TSZ;
    const int bx0 = bx * 16;              // 16x16 block origin
    const int by0 = by * 16;

    const int tid  = threadIdx.x;
    const int warp = tid >> 5;
    const int lane = tid & 31;
    const int base = tid * GPT;

    __shared__ short s_idx[NG];           // worst case: all gaussians
    __shared__ int wsum[8], wpre[8];
    __shared__ float4 sA[256];
    __shared__ float4 sB[256];
    __shared__ float2 sC[256];

    // --- Phase A: predicates (16 independent 8B loads per thread) ---
    unsigned mmask = 0;
    int lc = 0;
    #pragma unroll
    for (int k = 0; k < GPT; k++) {
        uint2 pb = g_spb[base + k];
        int xmin =  pb.x        & 255;
        int xmax = (pb.x >> 8)  & 255;
        int ymin = (pb.x >> 16) & 255;
        int ymax = (pb.x >> 24) & 255;
        bool clipped = (pb.y & 1u) != 0u;
        int X0 = clipped ? tx0 : bx0;
        int Y0 = clipped ? ty0 : by0;
        int SZ = clipped ? TSZ : 16;
        bool pred = (xmax >= X0) && (xmin < X0 + SZ) &&
                    (ymax >= Y0) && (ymin < Y0 + SZ);
        if (pred) { mmask |= (1u << k); lc++; }
    }

    // --- block-wide exclusive scan of lc ---
    int v = lc;
    #pragma unroll
    for (int d2 = 1; d2 < 32; d2 <<= 1) {
        int n = __shfl_up_sync(0xffffffffu, v, d2);
        if (lane >= d2) v += n;
    }
    if (lane == 31) wsum[warp] = v;
    __syncthreads();
    if (tid < 8) {
        int s = wsum[tid];
        #pragma unroll
        for (int d2 = 1; d2 < 8; d2 <<= 1) {
            int n = __shfl_up_sync(0xffu, s, d2);
            if (tid >= d2) s += n;
        }
        wpre[tid] = s;
    }
    __syncthreads();

    int offset = ((warp == 0) ? 0 : wpre[warp - 1]) + (v - lc);
    unsigned mm = mmask;
    while (mm) {
        int k = __ffs(mm) - 1;
        mm &= mm - 1;
        s_idx[offset++] = (short)(base + k);
    }
    const int cnt = wpre[7];
    __syncthreads();

    // --- Phase B: composite ---
    const int px = bx0 + (tid & 15);
    const int py = by0 + (tid >> 4);
    const float cx = (float)px + 0.5f;
    const float cy = (float)py + 0.5f;

    float T = 1.0f;
    float accR = 0.f, accG = 0.f, accB = 0.f, acc = 0.f, dnum = 0.f;

    for (int cbase = 0; cbase < cnt; cbase += 256) {
        int li = cbase + tid;
        if (li < cnt) {
            int gi = s_idx[li];
            sA[tid] = g_sA[gi];
            sB[tid] = g_sB[gi];
            sC[tid] = g_sC[gi];
        }
        __syncthreads();

        int m = cnt - cbase; if (m > 256) m = 256;
        for (int k = 0; k < m; k++) {
            float4 A = sA[k];
            float dx = cx - A.x;
            float dy = cy - A.y;
            float4 B = sB[k];
            float maha = dx*dx*A.z + dy*dy*A.w + dx*dy*B.x;
            if (maha <= 9.0f) {               // NaN -> false, matches jnp.where
                float alpha = fminf(__expf(-0.5f * maha) * B.y, 0.99f);
                if (alpha >= (1.0f / 255.0f)) {
                    float2 Cv = sC[k];
                    float w = T * alpha;
                    accR += w * B.z;
                    accG += w * B.w;
                    accB += w * Cv.x;
                    acc  += w;
                    dnum += w * Cv.y;
                    T *= (1.0f - alpha);
                }
            }
        }

        if (cbase + 256 < cnt) {
            if (__syncthreads_and(T < 1e-7f)) break;
        }
    }

    float bgr = bg[0], bgg = bg[1], bgb = bg[2];
    float Rv = accR + (1.0f - acc) * bgr;
    float Gv = accG + (1.0f - acc) * bgg;
    float Bv = accB + (1.0f - acc) * bgb;
    Rv = fminf(fmaxf(Rv, 0.0f), 1.0f);
    Gv = fminf(fmaxf(Gv, 0.0f), 1.0f);
    Bv = fminf(fmaxf(Bv, 0.0f), 1.0f);
    float A = fminf(fmaxf(acc, 0.0f), 1.0f);
    float depth = (acc > 0.0f) ? (dnum / fmaxf(acc, 1e-8f)) : 0.0f;

    int o = (py * W_IMG + px) * 5;
    out[o+0] = Rv;
    out[o+1] = Gv;
    out[o+2] = Bv;
    out[o+3] = A;
    out[o+4] = depth;
}

// ---------------------------------------------------------------------------
extern "C" void kernel_launch(void* const* d_in, const int* in_sizes, int n_in,
                              void* d_out, int out_size)
{
    const float* xyz     = (const float*)d_in[0];
    const float* cov     = (const float*)d_in[1];
    const float* colors  = (const float*)d_in[2];
    const float* opacity = (const float*)d_in[3];
    const float* w2c     = (const float*)d_in[4];
    const float* focal   = (const float*)d_in[5];
    const float* pp      = (const float*)d_in[6];
    const float* bg      = (const float*)d_in[7];
    float* out = (float*)d_out;

    prep_kernel<<<NG / 64, 64>>>(xyz, cov, colors, opacity, w2c, focal, pp);
    rank_kernel<<<dim3(16, 16), 256>>>();
    scatter_kernel<<<NG / 256, 256>>>();
    render_kernel<<<NBLK, 256>>>(bg, out);
}